// round 1
// baseline (speedup 1.0000x reference)
#include <cuda_runtime.h>

// Sizes are fixed by the problem: B=256, NU=NL=QU=QL=64.
#define NB  256
#define NUP 64
#define NLO 64
#define QUP 64
#define QLO 64

// Scratch for Taylor coefficient tensors A_n[i,k,l], n=0..4.
// A0..A3 packed as float4, A4 separate. 16 MB + 4 MB, __device__ globals
// (allocation-free per harness rules).
__device__ float4 g_A03[NB * NLO * QUP];
__device__ float  g_A4 [NB * NLO * QUP];

// ---------------------------------------------------------------------------
// Kernel 1: A_n[i,k,l] = ((-1)^n / n!) * sum_m P[i,k,m] * u[l,m]^n
// where u[l,m] = ((m-l)/64)^2 depends only on d = m-l (Toeplitz).
// Grid: 512 blocks = (i, k-half). Block: 512 threads.
//   lane -> l (32 l's), warp&1 -> l-half, warp>>1 -> k-group of 4.
// ---------------------------------------------------------------------------
__global__ __launch_bounds__(512, 2)
void drn_k1(const float* __restrict__ P)
{
    __shared__ float sP[32 * 64];     // [k_local][m]
    __shared__ float sUp[127 * 5];    // powers 1..4, stride 5 (conflict-free)

    const int tid = threadIdx.x;
    const int i   = blockIdx.x >> 1;
    const int kh  = blockIdx.x & 1;

    const float* Pi = P + (i * NLO + kh * 32) * QLO;
    #pragma unroll
    for (int r = 0; r < 4; ++r)
        sP[tid + 512 * r] = Pi[tid + 512 * r];

    if (tid < 127) {
        float dd = (float)(tid - 63) * (1.0f / 64.0f);
        float u  = dd * dd;
        float u2 = u * u;
        sUp[tid * 5 + 0] = -u;                         // (-1)^1/1! * u
        sUp[tid * 5 + 1] = 0.5f * u2;                  // (+1)/2!  * u^2
        sUp[tid * 5 + 2] = -(1.0f / 6.0f) * (u2 * u);  // (-1)/3!  * u^3
        sUp[tid * 5 + 3] = (1.0f / 24.0f) * (u2 * u2); // (+1)/4!  * u^4
        sUp[tid * 5 + 4] = 0.0f;                       // pad
    }
    __syncthreads();

    const int lane = tid & 31;
    const int warp = tid >> 5;
    const int l  = lane + 32 * (warp & 1);
    const int kg = (warp >> 1) * 4;   // local k base within the 32-k half

    float a0[4] = {0.f, 0.f, 0.f, 0.f};
    float a1[4] = {0.f, 0.f, 0.f, 0.f};
    float a2[4] = {0.f, 0.f, 0.f, 0.f};
    float a3[4] = {0.f, 0.f, 0.f, 0.f};
    float a4[4] = {0.f, 0.f, 0.f, 0.f};

    #pragma unroll 8
    for (int m = 0; m < 64; ++m) {
        const float* up = &sUp[(m - l + 63) * 5];  // lanes: stride-5 -> no conflicts
        const float u1 = up[0];
        const float u2 = up[1];
        const float u3 = up[2];
        const float u4 = up[3];
        #pragma unroll
        for (int kk = 0; kk < 4; ++kk) {
            const float p = sP[(kg + kk) * 64 + m];  // broadcast across lanes
            a0[kk] += p;
            a1[kk] = fmaf(p, u1, a1[kk]);
            a2[kk] = fmaf(p, u2, a2[kk]);
            a3[kk] = fmaf(p, u3, a3[kk]);
            a4[kk] = fmaf(p, u4, a4[kk]);
        }
    }

    #pragma unroll
    for (int kk = 0; kk < 4; ++kk) {
        const int k   = kh * 32 + kg + kk;
        const int row = (i * NLO + k) * QUP + l;
        g_A03[row] = make_float4(a0[kk], a1[kk], a2[kk], a3[kk]);
        g_A4[row]  = a4[kk];
    }
}

// ---------------------------------------------------------------------------
// Kernel 2: per batch row i (grid 256):
//   Pw[j,k,l]   = Horner(w[j,k]; A0..A4[i,k,l])
//   logsum[j,l] = sum over k of log(clip(Pw))   (computed as log of 8-products)
//   out[i,j,:]  = softmax_l(logsum + exponent_B[j,:])
// lanes -> j, so all A loads are smem broadcasts shared by 32 j's.
// ---------------------------------------------------------------------------
#define SM_A03  (4096 * 16)           // 65536
#define SM_A4   (4096 * 4)            // 16384
#define SM_WT   (4096 * 4)            // 16384
#define SM_LS   (64 * 65 * 4)         // 16640 (pad stride 65: conflict-free)
#define K2_SMEM (SM_A03 + SM_A4 + SM_WT + SM_LS)   // 114944 B

__global__ __launch_bounds__(512, 2)
void drn_k2(const float* __restrict__ weight,
            const float* __restrict__ bias_abs,
            const float* __restrict__ bias_q,
            const float* __restrict__ lam_abs,
            const float* __restrict__ lam_q,
            float* __restrict__ out)
{
    extern __shared__ __align__(16) unsigned char smem_raw[];
    float4* sA03 = reinterpret_cast<float4*>(smem_raw);
    float*  sA4  = reinterpret_cast<float*>(smem_raw + SM_A03);
    float*  swT  = reinterpret_cast<float*>(smem_raw + SM_A03 + SM_A4);   // [k][j]
    float*  sLs  = reinterpret_cast<float*>(smem_raw + SM_A03 + SM_A4 + SM_WT); // [j][l] pad65

    const int i   = blockIdx.x;
    const int tid = threadIdx.x;

    const float4* gA  = g_A03 + i * 4096;
    const float*  gA4 = g_A4  + i * 4096;
    #pragma unroll
    for (int r = 0; r < 8; ++r) {
        const int idx = tid + 512 * r;
        sA03[idx] = gA[idx];
        sA4[idx]  = gA4[idx];
        const int j = idx >> 6;
        const int k = idx & 63;
        swT[k * 64 + j] = weight[idx];   // transpose: conflict-free reads later
    }
    __syncthreads();

    const int lane = tid & 31;
    const int warp = tid >> 5;
    const int j  = lane + 32 * (warp & 1);
    const int lb = (warp >> 1) * 8;

    float acc[8];
    #pragma unroll
    for (int li = 0; li < 8; ++li) acc[li] = 0.f;

    for (int k0 = 0; k0 < 64; k0 += 8) {
        float prod[8];
        #pragma unroll
        for (int li = 0; li < 8; ++li) prod[li] = 1.f;

        #pragma unroll
        for (int kk = 0; kk < 8; ++kk) {
            const int k = k0 + kk;
            const float w = swT[k * 64 + j];        // coalesced over lanes
            #pragma unroll
            for (int li = 0; li < 8; ++li) {
                const int idx  = k * 64 + lb + li;
                const float4 a = sA03[idx];          // broadcast LDS.128
                float pw = fmaf(w, sA4[idx], a.w);   // broadcast LDS.32
                pw = fmaf(w, pw, a.z);
                pw = fmaf(w, pw, a.y);
                pw = fmaf(w, pw, a.x);
                pw = fminf(fmaxf(pw, 1e-15f), 1e15f);
                prod[li] *= pw;
            }
        }
        #pragma unroll
        for (int li = 0; li < 8; ++li)
            acc[li] += __logf(prod[li]);   // log of 8-product == sum of 8 logs
    }

    // exponent_B[j,l] = -bias_q[j]*(s-lam_q[j])^2 - bias_abs[j]*|s-lam_abs[j]|
    const float ba = bias_abs[j];
    const float bq = bias_q[j];
    const float la = lam_abs[j];
    const float lq = lam_q[j];
    #pragma unroll
    for (int li = 0; li < 8; ++li) {
        const int l = lb + li;
        const float sq = (float)l * (1.0f / 64.0f);
        const float dq = sq - lq;
        const float da = sq - la;
        sLs[j * 65 + l] = acc[li] - bq * dq * dq - ba * fabsf(da);
    }
    __syncthreads();

    // Softmax over l per (i,j): each warp handles 4 j-rows, 2 values per lane.
    #pragma unroll
    for (int r = 0; r < 4; ++r) {
        const int j2 = warp * 4 + r;
        const float v0 = sLs[j2 * 65 + lane];
        const float v1 = sLs[j2 * 65 + 32 + lane];
        float mx = fmaxf(v0, v1);
        #pragma unroll
        for (int o = 16; o; o >>= 1)
            mx = fmaxf(mx, __shfl_xor_sync(0xffffffffu, mx, o));
        const float e0 = __expf(v0 - mx);
        const float e1 = __expf(v1 - mx);
        float s = e0 + e1;
        #pragma unroll
        for (int o = 16; o; o >>= 1)
            s += __shfl_xor_sync(0xffffffffu, s, o);
        const float inv = 1.0f / s;
        out[(i * NUP + j2) * QUP + lane]      = e0 * inv;
        out[(i * NUP + j2) * QUP + 32 + lane] = e1 * inv;
    }
}

// ---------------------------------------------------------------------------
extern "C" void kernel_launch(void* const* d_in, const int* in_sizes, int n_in,
                              void* d_out, int out_size)
{
    const float* P        = (const float*)d_in[0];
    const float* weight   = (const float*)d_in[1];
    const float* bias_abs = (const float*)d_in[2];
    const float* bias_q   = (const float*)d_in[3];
    const float* lam_abs  = (const float*)d_in[4];
    const float* lam_q    = (const float*)d_in[5];
    float* out = (float*)d_out;

    // Opt-in to >48KB dynamic smem (idempotent; not a stream op, capture-safe).
    cudaFuncSetAttribute(drn_k2, cudaFuncAttributeMaxDynamicSharedMemorySize, K2_SMEM);

    drn_k1<<<512, 512>>>(P);
    drn_k2<<<256, 512, K2_SMEM>>>(weight, bias_abs, bias_q, lam_abs, lam_q, out);
}

// round 2
// speedup vs baseline: 1.1577x; 1.1577x over previous
#include <cuda_runtime.h>

// Sizes fixed by the problem: B=256, NU=NL=QU=QL=64.
#define NB  256
#define NUP 64
#define NLO 64
#define QUP 64
#define QLO 64

// Scratch: cumulant coefficient tensor C[i][k][l] = (c1,c2,c3,c4), 16 MB.
__device__ float4 g_C[NB * NLO * QUP];

// ---- packed f32x2 helpers ---------------------------------------------------
__device__ __forceinline__ void ffma2(unsigned long long& acc,
                                      unsigned long long a, unsigned long long b) {
    asm("fma.rn.f32x2 %0, %1, %2, %0;" : "+l"(acc) : "l"(a), "l"(b));
}
__device__ __forceinline__ unsigned long long pack2(float x, float y) {
    unsigned long long r;
    asm("mov.b64 %0, {%1, %2};" : "=l"(r) : "f"(x), "f"(y));
    return r;
}
__device__ __forceinline__ float2 unpack2(unsigned long long v) {
    float2 f;
    asm("mov.b64 {%0, %1}, %2;" : "=f"(f.x), "=f"(f.y) : "l"(v));
    return f;
}

// ---------------------------------------------------------------------------
// Kernel 1: raw moments -> cumulant coefficients.
//   M_n[i,k,l] = sum_m P[i,k,m] * u^n,  u = ((m-l)/64)^2  (Toeplitz in m-l)
//   m_n = M_n / M_0;  kappa_n -> C_n = kappa_n / n!
// Grid 512 = (i, k-half), block 512. lane->l, warp&1->l-half, warp>>1->k-grp4.
// ---------------------------------------------------------------------------
__global__ __launch_bounds__(512, 2)
void drn_k1(const float* __restrict__ P)
{
    __shared__ unsigned long long sPd[32 * 64];  // (p,p) duplicated pairs
    __shared__ float4 sUp[128];                  // [d] = (u, u^2, u^3, u^4)

    const int tid = threadIdx.x;
    const int i   = blockIdx.x >> 1;
    const int kh  = blockIdx.x & 1;

    const float* Pi = P + (i * NLO + kh * 32) * QLO;
    #pragma unroll
    for (int r = 0; r < 4; ++r) {
        const int idx = tid + 512 * r;
        const float v = Pi[idx];
        sPd[idx] = pack2(v, v);
    }
    if (tid < 127) {
        const float dd = (float)(tid - 63) * (1.0f / 64.0f);
        const float u  = dd * dd;
        const float u2 = u * u;
        sUp[tid] = make_float4(u, u2, u2 * u, u2 * u2);
    }
    __syncthreads();

    const int lane = tid & 31;
    const int warp = tid >> 5;
    const int l  = lane + 32 * (warp & 1);
    const int kg = (warp >> 1) * 4;

    unsigned long long A12[4], A34[4];
    float a0[4];
    #pragma unroll
    for (int kk = 0; kk < 4; ++kk) { A12[kk] = 0ULL; A34[kk] = 0ULL; a0[kk] = 0.f; }

    const unsigned long long* sPdm = sPd + kg * 64;
    #pragma unroll 8
    for (int m = 0; m < 64; ++m) {
        const ulonglong2 uv =
            reinterpret_cast<const ulonglong2*>(sUp)[m - l + 63];  // conflict-free
        #pragma unroll
        for (int kk = 0; kk < 4; ++kk) {
            const unsigned long long pd = sPdm[kk * 64 + m];       // broadcast
            ffma2(A12[kk], pd, uv.x);
            ffma2(A34[kk], pd, uv.y);
            a0[kk] += __uint_as_float((unsigned int)pd);           // low half (free)
        }
    }

    #pragma unroll
    for (int kk = 0; kk < 4; ++kk) {
        const float  r  = 1.0f / a0[kk];
        const float2 v12 = unpack2(A12[kk]);
        const float2 v34 = unpack2(A34[kk]);
        const float m1 = v12.x * r, m2 = v12.y * r;
        const float m3 = v34.x * r, m4 = v34.y * r;
        const float m1s = m1 * m1;
        const float c1 = m1;
        const float c2 = 0.5f * (m2 - m1s);
        const float c3 = (1.0f / 6.0f) * (m3 - 3.0f * m1 * m2 + 2.0f * m1s * m1);
        const float c4 = (1.0f / 24.0f) * (m4 - 4.0f * m1 * m3 - 3.0f * m2 * m2
                                           + 12.0f * m1s * m2 - 6.0f * m1s * m1s);
        const int k = kh * 32 + kg + kk;
        g_C[(i * NLO + k) * QUP + l] = make_float4(c1, c2, c3, c4);
    }
}

// ---------------------------------------------------------------------------
// Kernel 2: per i, GEMM  logsum[j,l] = sum_{k,n} t^n[j,k] * C_n[i,k,l]
// (t = -w), then + exponent_B, softmax over l.
// Block 256 = 16(tj) x 16(tl); thread computes 4j x 4l via f32x2 outer product.
// K' = 256 processed in 8 chunks of 32 (k-chunks of 8), SW/SC staged in smem.
// ---------------------------------------------------------------------------
__global__ __launch_bounds__(256)
void drn_k2(const float* __restrict__ weight,
            const float* __restrict__ bias_abs,
            const float* __restrict__ bias_q,
            const float* __restrict__ lam_abs,
            const float* __restrict__ lam_q,
            float* __restrict__ out)
{
    __shared__ float sW[32 * 64];                 // [K''][j]        8 KB
    __shared__ unsigned long long sCd[32 * 64];   // [K''][l] (c,c) 16 KB
    __shared__ float sLs[64 * 65];                // logsum staging 16.6 KB
    __shared__ float sBa[64], sBq[64], sLa[64], sLq[64];

    const int i   = blockIdx.x;
    const int tid = threadIdx.x;
    const int tj  = tid & 15;
    const int tl  = tid >> 4;

    if (tid < 64) {
        sBa[tid] = bias_abs[tid];
        sBq[tid] = bias_q[tid];
        sLa[tid] = lam_abs[tid];
        sLq[tid] = lam_q[tid];
    }

    const int jlA = tid & 63;          // j (for W) / l (for C)
    const int kqA = tid >> 6;          // 0..3 ; second slice uses kq+4
    const float4* gCi = g_C + i * 4096;

    unsigned long long acc00 = 0, acc01 = 0, acc02 = 0, acc03 = 0;
    unsigned long long acc10 = 0, acc11 = 0, acc12 = 0, acc13 = 0;

    // prefetch chunk 0
    float4 cA = gCi[(0 + kqA) * 64 + jlA];
    float4 cB = gCi[(4 + kqA) * 64 + jlA];
    float  wA = weight[jlA * 64 + kqA];
    float  wB = weight[jlA * 64 + kqA + 4];

    for (int c = 0; c < 8; ++c) {
        __syncthreads();   // previous chunk's compute done before overwrite
        {
            // store W powers (t = -w)
            float t = -wA, t2 = t * t;
            sW[(kqA * 4 + 0) * 64 + jlA] = t;
            sW[(kqA * 4 + 1) * 64 + jlA] = t2;
            sW[(kqA * 4 + 2) * 64 + jlA] = t2 * t;
            sW[(kqA * 4 + 3) * 64 + jlA] = t2 * t2;
            t = -wB; t2 = t * t;
            sW[((kqA + 4) * 4 + 0) * 64 + jlA] = t;
            sW[((kqA + 4) * 4 + 1) * 64 + jlA] = t2;
            sW[((kqA + 4) * 4 + 2) * 64 + jlA] = t2 * t;
            sW[((kqA + 4) * 4 + 3) * 64 + jlA] = t2 * t2;
            // store duplicated C pairs
            sCd[(kqA * 4 + 0) * 64 + jlA] = pack2(cA.x, cA.x);
            sCd[(kqA * 4 + 1) * 64 + jlA] = pack2(cA.y, cA.y);
            sCd[(kqA * 4 + 2) * 64 + jlA] = pack2(cA.z, cA.z);
            sCd[(kqA * 4 + 3) * 64 + jlA] = pack2(cA.w, cA.w);
            sCd[((kqA + 4) * 4 + 0) * 64 + jlA] = pack2(cB.x, cB.x);
            sCd[((kqA + 4) * 4 + 1) * 64 + jlA] = pack2(cB.y, cB.y);
            sCd[((kqA + 4) * 4 + 2) * 64 + jlA] = pack2(cB.z, cB.z);
            sCd[((kqA + 4) * 4 + 3) * 64 + jlA] = pack2(cB.w, cB.w);
        }
        __syncthreads();

        if (c < 7) {   // prefetch next chunk
            const int kb = (c + 1) * 8;
            cA = gCi[(kb + kqA) * 64 + jlA];
            cB = gCi[(kb + 4 + kqA) * 64 + jlA];
            wA = weight[jlA * 64 + kb + kqA];
            wB = weight[jlA * 64 + kb + kqA + 4];
        }

        #pragma unroll 8
        for (int kk = 0; kk < 32; ++kk) {
            const ulonglong2 a =
                reinterpret_cast<const ulonglong2*>(sW + kk * 64)[tj];     // (j0,j1),(j2,j3)
            const ulonglong2 b01 =
                reinterpret_cast<const ulonglong2*>(sCd + kk * 64)[tl * 2];     // (l0,l0),(l1,l1)
            const ulonglong2 b23 =
                reinterpret_cast<const ulonglong2*>(sCd + kk * 64)[tl * 2 + 1]; // (l2,l2),(l3,l3)
            ffma2(acc00, a.x, b01.x); ffma2(acc10, a.y, b01.x);
            ffma2(acc01, a.x, b01.y); ffma2(acc11, a.y, b01.y);
            ffma2(acc02, a.x, b23.x); ffma2(acc12, a.y, b23.x);
            ffma2(acc03, a.x, b23.y); ffma2(acc13, a.y, b23.y);
        }
    }

    // ---- epilogue: + exponent_B, stage to sLs --------------------------------
    const int j0 = tj * 4, l0 = tl * 4;
    {
        float2 v;
        float lsv[2][4][2];  // [jpair][l][lane-in-pair]
        v = unpack2(acc00); lsv[0][0][0] = v.x; lsv[0][0][1] = v.y;
        v = unpack2(acc01); lsv[0][1][0] = v.x; lsv[0][1][1] = v.y;
        v = unpack2(acc02); lsv[0][2][0] = v.x; lsv[0][2][1] = v.y;
        v = unpack2(acc03); lsv[0][3][0] = v.x; lsv[0][3][1] = v.y;
        v = unpack2(acc10); lsv[1][0][0] = v.x; lsv[1][0][1] = v.y;
        v = unpack2(acc11); lsv[1][1][0] = v.x; lsv[1][1][1] = v.y;
        v = unpack2(acc12); lsv[1][2][0] = v.x; lsv[1][2][1] = v.y;
        v = unpack2(acc13); lsv[1][3][0] = v.x; lsv[1][3][1] = v.y;

        #pragma unroll
        for (int p = 0; p < 2; ++p)
            #pragma unroll
            for (int h = 0; h < 2; ++h) {
                const int j  = j0 + p * 2 + h;
                const float ba = sBa[j], bq = sBq[j], la = sLa[j], lq = sLq[j];
                #pragma unroll
                for (int q = 0; q < 4; ++q) {
                    const int l = l0 + q;
                    const float sq = (float)l * (1.0f / 64.0f);
                    const float dq = sq - lq;
                    const float da = sq - la;
                    sLs[j * 65 + l] = lsv[p][q][h] - bq * dq * dq - ba * fabsf(da);
                }
            }
    }
    __syncthreads();

    // ---- softmax over l: 8 warps x 8 rows ------------------------------------
    const int lane = tid & 31;
    const int warp = tid >> 5;
    #pragma unroll
    for (int r = 0; r < 8; ++r) {
        const int j2 = warp * 8 + r;
        const float v0 = sLs[j2 * 65 + lane];
        const float v1 = sLs[j2 * 65 + 32 + lane];
        float mx = fmaxf(v0, v1);
        #pragma unroll
        for (int o = 16; o; o >>= 1)
            mx = fmaxf(mx, __shfl_xor_sync(0xffffffffu, mx, o));
        const float e0 = __expf(v0 - mx);
        const float e1 = __expf(v1 - mx);
        float s = e0 + e1;
        #pragma unroll
        for (int o = 16; o; o >>= 1)
            s += __shfl_xor_sync(0xffffffffu, s, o);
        const float inv = 1.0f / s;
        out[(i * NUP + j2) * QUP + lane]      = e0 * inv;
        out[(i * NUP + j2) * QUP + 32 + lane] = e1 * inv;
    }
}

// ---------------------------------------------------------------------------
extern "C" void kernel_launch(void* const* d_in, const int* in_sizes, int n_in,
                              void* d_out, int out_size)
{
    const float* P        = (const float*)d_in[0];
    const float* weight   = (const float*)d_in[1];
    const float* bias_abs = (const float*)d_in[2];
    const float* bias_q   = (const float*)d_in[3];
    const float* lam_abs  = (const float*)d_in[4];
    const float* lam_q    = (const float*)d_in[5];
    float* out = (float*)d_out;

    drn_k1<<<512, 512>>>(P);
    drn_k2<<<256, 256>>>(weight, bias_abs, bias_q, lam_abs, lam_q, out);
}

// round 4
// speedup vs baseline: 1.6836x; 1.4542x over previous
#include <cuda_runtime.h>
#include <cuda_bf16.h>
#include <cstdint>

// B=256, NU=NL=QU=QL=64. One CTA = 2 batch rows. 128 CTAs x 256 threads.
#define THREADS 256

// ---------------- smem byte offsets (all tiles SW128-swizzled) --------------
#define SM_P    0u          // [128 rows (ii,k)][64 bf16]   16 KB
#define SM_UH   16384u      // [256 rows (l*4+n)][64 bf16]  32 KB
#define SM_UL   49152u      //                              32 KB
#define SM_C1H  81920u      // [128 rows (ii*64+l)][64 bf16] 16 KB each
#define SM_C1L  98304u
#define SM_C2   114688u
#define SM_C3   131072u
#define SM_C4   147456u
#define SM_TH   163840u     // [64 j][64 bf16] 8 KB each
#define SM_T2   172032u
#define SM_T3   180224u
#define SM_T4   188416u
#define SM_LS   SM_UH       // overlay: [128 il][65 f32] = 33280 B (U dead)
#define SM_MISC 196608u
#define SMEM_TOTAL (SM_MISC + 2048u)   // 198656 B

__device__ __forceinline__ uint32_t sw128(uint32_t o) { return o ^ ((o >> 3) & 0x70u); }

// m16n8k16 row.col bf16 -> f32 (sm_80-baseline PTX; HMMA on Blackwell)
__device__ __forceinline__ void mma16816(float acc[4], const uint32_t a[4],
                                         const uint32_t b[2]) {
    asm volatile(
        "mma.sync.aligned.m16n8k16.row.col.f32.bf16.bf16.f32 "
        "{%0,%1,%2,%3}, {%4,%5,%6,%7}, {%8,%9}, {%0,%1,%2,%3};"
        : "+f"(acc[0]), "+f"(acc[1]), "+f"(acc[2]), "+f"(acc[3])
        : "r"(a[0]), "r"(a[1]), "r"(a[2]), "r"(a[3]), "r"(b[0]), "r"(b[1]));
}

// A fragment: a0=(row g,k), a1=(row g+8,k), a2=(row g,k+8), a3=(row g+8,k+8)
__device__ __forceinline__ void ldA(const char* sm, uint32_t base, uint32_t o0,
                                    uint32_t a[4]) {
    a[0] = *(const uint32_t*)(sm + sw128(base + o0));
    a[1] = *(const uint32_t*)(sm + sw128(base + o0 + 1024));
    a[2] = *(const uint32_t*)(sm + sw128(base + o0 + 16));
    a[3] = *(const uint32_t*)(sm + sw128(base + o0 + 1040));
}
// B fragment from [n][k] tile: b0=(n=g, k pair), b1=(n=g, k pair+8)
__device__ __forceinline__ void ldB(const char* sm, uint32_t base, uint32_t o0,
                                    uint32_t b[2]) {
    b[0] = *(const uint32_t*)(sm + sw128(base + o0));
    b[1] = *(const uint32_t*)(sm + sw128(base + o0 + 16));
}

__global__ void __launch_bounds__(THREADS, 1)
drn_fused(const float* __restrict__ P, const float* __restrict__ weight,
          const float* __restrict__ bias_abs, const float* __restrict__ bias_q,
          const float* __restrict__ lam_abs, const float* __restrict__ lam_q,
          float* __restrict__ out)
{
    extern __shared__ __align__(16) char sm[];
    float* a0inv = (float*)(sm + SM_MISC);          // 128 floats
    float* sBa   = (float*)(sm + SM_MISC + 512);
    float* sBq   = (float*)(sm + SM_MISC + 768);
    float* sLa   = (float*)(sm + SM_MISC + 1024);
    float* sLq   = (float*)(sm + SM_MISC + 1280);

    const int tid = threadIdx.x;
    const int i0  = blockIdx.x * 2;

    // ---- fill P tile (bf16) + row sums ------------------------------------
    {
        const int r = tid >> 1, h = tid & 1;
        const float* src = P + ((size_t)(i0 + (r >> 6)) * 64 + (r & 63)) * 64 + h * 32;
        float s = 0.f;
        #pragma unroll
        for (int q = 0; q < 8; ++q) {
            const float4 f = ((const float4*)src)[q];
            s += f.x + f.y + f.z + f.w;
            const uint32_t off = (uint32_t)r * 128 + (h * 32 + q * 4) * 2;
            *(__nv_bfloat162*)(sm + SM_P + sw128(off))     = __floats2bfloat162_rn(f.x, f.y);
            *(__nv_bfloat162*)(sm + SM_P + sw128(off + 4)) = __floats2bfloat162_rn(f.z, f.w);
        }
        s += __shfl_xor_sync(0xffffffffu, s, 1);
        a0inv[r] = 1.0f / s;
    }

    // ---- fill U table hi/lo: row r = l*4+n holds u^(n+1), u=((l-m)/64)^2 ---
    {
        const int r = tid, l = r >> 2, n = r & 3;
        #pragma unroll 4
        for (int m2 = 0; m2 < 32; ++m2) {
            const int m = m2 * 2;
            float d0 = (float)(l - m) * (1.f / 64.f);
            float d1 = (float)(l - m - 1) * (1.f / 64.f);
            float u0 = d0 * d0, u1 = d1 * d1;
            float w0 = u0 * u0, w1 = u1 * u1;
            float v0 = (n == 0) ? u0 : (n == 1) ? w0 : (n == 2) ? w0 * u0 : w0 * w0;
            float v1 = (n == 0) ? u1 : (n == 1) ? w1 : (n == 2) ? w1 * u1 : w1 * w1;
            const __nv_bfloat162 hi = __floats2bfloat162_rn(v0, v1);
            const float r0 = v0 - __bfloat162float(hi.x);
            const float r1 = v1 - __bfloat162float(hi.y);
            const uint32_t off = (uint32_t)r * 128 + m * 2;
            *(__nv_bfloat162*)(sm + SM_UH + sw128(off)) = hi;
            *(__nv_bfloat162*)(sm + SM_UL + sw128(off)) = __floats2bfloat162_rn(r0, r1);
        }
    }

    // ---- fill T power tiles: row j holds t^n[j,k], t = -w ------------------
    {
        const int j = tid >> 2, kq = (tid & 3) * 16;
        const float* wr = weight + j * 64 + kq;
        #pragma unroll
        for (int q = 0; q < 8; ++q) {
            const float t0 = -wr[q * 2], t1 = -wr[q * 2 + 1];
            const float s0 = t0 * t0,   s1 = t1 * t1;
            const uint32_t off = (uint32_t)j * 128 + (kq + q * 2) * 2;
            *(__nv_bfloat162*)(sm + SM_TH + sw128(off)) = __floats2bfloat162_rn(t0, t1);
            *(__nv_bfloat162*)(sm + SM_T2 + sw128(off)) = __floats2bfloat162_rn(s0, s1);
            *(__nv_bfloat162*)(sm + SM_T3 + sw128(off)) = __floats2bfloat162_rn(s0 * t0, s1 * t1);
            *(__nv_bfloat162*)(sm + SM_T4 + sw128(off)) = __floats2bfloat162_rn(s0 * s0, s1 * s1);
        }
    }
    if (tid < 64) {
        sBa[tid] = bias_abs[tid]; sBq[tid] = bias_q[tid];
        sLa[tid] = lam_abs[tid];  sLq[tid] = lam_q[tid];
    }
    __syncthreads();

    const int lane = tid & 31, wid = tid >> 5;
    const int g = lane >> 2, c = lane & 3;
    const int mr = wid * 16;
    const uint32_t aoff = (uint32_t)(mr + g) * 128 + c * 4;

    // ================= GEMM1: moments, then cumulants -> C tiles ============
    #pragma unroll 1
    for (int ch = 0; ch < 4; ++ch) {
        float acc[8][4];
        #pragma unroll
        for (int t = 0; t < 8; ++t)
            acc[t][0] = acc[t][1] = acc[t][2] = acc[t][3] = 0.f;

        #pragma unroll
        for (int pass = 0; pass < 2; ++pass) {
            const uint32_t SB = pass ? SM_UL : SM_UH;
            #pragma unroll
            for (int ks = 0; ks < 4; ++ks) {
                uint32_t a[4];
                ldA(sm, SM_P, aoff + ks * 32, a);
                #pragma unroll
                for (int t = 0; t < 8; ++t) {
                    uint32_t b[2];
                    const uint32_t boff =
                        (uint32_t)(ch * 64 + t * 8 + g) * 128 + c * 4 + ks * 32;
                    ldB(sm, SB, boff, b);
                    mma16816(acc[t], a, b);
                }
            }
        }
        // epilogue: lane-pair exchange, fp32 cumulants, bf16 C stores
        #pragma unroll
        for (int t = 0; t < 8; ++t) {
            const float r0 = __shfl_xor_sync(0xffffffffu, acc[t][0], 1);
            const float r1 = __shfl_xor_sync(0xffffffffu, acc[t][1], 1);
            const float r2 = __shfl_xor_sync(0xffffffffu, acc[t][2], 1);
            const float r3 = __shfl_xor_sync(0xffffffffu, acc[t][3], 1);
            int row; float M1, M2, M3, M4;
            if ((c & 1) == 0) { row = mr + g;     M1 = acc[t][0]; M2 = acc[t][1]; M3 = r0; M4 = r1; }
            else              { row = mr + g + 8; M1 = r2; M2 = r3; M3 = acc[t][2]; M4 = acc[t][3]; }
            const int l = ch * 16 + t * 2 + (c >> 1);
            const float ai = a0inv[row];
            const float m1 = M1 * ai, m2 = M2 * ai, m3 = M3 * ai, m4 = M4 * ai;
            const float m1s = m1 * m1;
            const float c1 = m1;
            const float c2 = 0.5f * (m2 - m1s);
            const float c3 = (1.f / 6.f) * (m3 - 3.f * m1 * m2 + 2.f * m1s * m1);
            const float c4 = (1.f / 24.f) * (m4 - 4.f * m1 * m3 - 3.f * m2 * m2
                                             + 12.f * m1s * m2 - 6.f * m1s * m1s);
            const uint32_t off =
                (uint32_t)(((row >> 6) * 64 + l) * 128 + (row & 63) * 2);
            const __nv_bfloat16 c1h = __float2bfloat16_rn(c1);
            *(__nv_bfloat16*)(sm + SM_C1H + sw128(off)) = c1h;
            *(__nv_bfloat16*)(sm + SM_C1L + sw128(off)) =
                __float2bfloat16_rn(c1 - __bfloat162float(c1h));
            *(__nv_bfloat16*)(sm + SM_C2 + sw128(off)) = __float2bfloat16_rn(c2);
            *(__nv_bfloat16*)(sm + SM_C3 + sw128(off)) = __float2bfloat16_rn(c3);
            *(__nv_bfloat16*)(sm + SM_C4 + sw128(off)) = __float2bfloat16_rn(c4);
        }
    }
    __syncthreads();

    // ================= GEMM2: logsum^T[(ii,l), j] ============================
    {
        float acc[8][4];
        #pragma unroll
        for (int t = 0; t < 8; ++t)
            acc[t][0] = acc[t][1] = acc[t][2] = acc[t][3] = 0.f;

        const uint32_t pA[5] = {SM_C1H, SM_C1L, SM_C2, SM_C3, SM_C4};
        const uint32_t pB[5] = {SM_TH,  SM_TH,  SM_T2, SM_T3, SM_T4};
        #pragma unroll
        for (int p = 0; p < 5; ++p) {
            #pragma unroll
            for (int ks = 0; ks < 4; ++ks) {
                uint32_t a[4];
                ldA(sm, pA[p], aoff + ks * 32, a);
                #pragma unroll
                for (int t = 0; t < 8; ++t) {
                    uint32_t b[2];
                    const uint32_t boff = (uint32_t)(t * 8 + g) * 128 + c * 4 + ks * 32;
                    ldB(sm, pB[p], boff, b);
                    mma16816(acc[t], a, b);
                }
            }
        }

        // epilogue: + exponent_B, stage to sLs
        float* ls = (float*)(sm + SM_LS);
        const int rowA = mr + g, rowB = rowA + 8;
        const float slA = (float)(rowA & 63) * (1.f / 64.f);
        const float slB = (float)(rowB & 63) * (1.f / 64.f);
        #pragma unroll
        for (int t = 0; t < 8; ++t) {
            const int j0 = t * 8 + c * 2, j1 = j0 + 1;
            const float bq0 = sBq[j0], lq0 = sLq[j0], ba0 = sBa[j0], la0 = sLa[j0];
            const float bq1 = sBq[j1], lq1 = sLq[j1], ba1 = sBa[j1], la1 = sLa[j1];
            float d;
            d = slA - lq0; const float e00 = acc[t][0] - bq0 * d * d - ba0 * fabsf(slA - la0);
            d = slA - lq1; const float e01 = acc[t][1] - bq1 * d * d - ba1 * fabsf(slA - la1);
            d = slB - lq0; const float e10 = acc[t][2] - bq0 * d * d - ba0 * fabsf(slB - la0);
            d = slB - lq1; const float e11 = acc[t][3] - bq1 * d * d - ba1 * fabsf(slB - la1);
            ls[rowA * 65 + j0] = e00; ls[rowA * 65 + j1] = e01;
            ls[rowB * 65 + j0] = e10; ls[rowB * 65 + j1] = e11;
        }
    }
    __syncthreads();

    // ================= softmax over l, write out =============================
    {
        const float* ls = (const float*)(sm + SM_LS);
        const int rid = tid >> 1, h = tid & 1;
        const int ii = rid >> 6, j = rid & 63;
        const int base = ii * 64 + h * 32;
        float v[32], mx = -1e30f;
        #pragma unroll
        for (int q = 0; q < 32; ++q) {
            v[q] = ls[(base + q) * 65 + j];
            mx = fmaxf(mx, v[q]);
        }
        mx = fmaxf(mx, __shfl_xor_sync(0xffffffffu, mx, 1));
        float s = 0.f;
        #pragma unroll
        for (int q = 0; q < 32; ++q) { v[q] = __expf(v[q] - mx); s += v[q]; }
        s += __shfl_xor_sync(0xffffffffu, s, 1);
        const float inv = 1.0f / s;
        float4* ob = (float4*)(out + ((size_t)(i0 + ii) * 64 + j) * 64 + h * 32);
        #pragma unroll
        for (int q = 0; q < 8; ++q)
            ob[q] = make_float4(v[4 * q] * inv, v[4 * q + 1] * inv,
                                v[4 * q + 2] * inv, v[4 * q + 3] * inv);
    }
}

// ---------------------------------------------------------------------------
extern "C" void kernel_launch(void* const* d_in, const int* in_sizes, int n_in,
                              void* d_out, int out_size)
{
    const float* P        = (const float*)d_in[0];
    const float* weight   = (const float*)d_in[1];
    const float* bias_abs = (const float*)d_in[2];
    const float* bias_q   = (const float*)d_in[3];
    const float* lam_abs  = (const float*)d_in[4];
    const float* lam_q    = (const float*)d_in[5];
    float* out = (float*)d_out;

    cudaFuncSetAttribute(drn_fused, cudaFuncAttributeMaxDynamicSharedMemorySize,
                         SMEM_TOTAL);
    drn_fused<<<128, THREADS, SMEM_TOTAL>>>(P, weight, bias_abs, bias_q,
                                            lam_abs, lam_q, out);
}

// round 5
// speedup vs baseline: 3.0950x; 1.8383x over previous
#include <cuda_runtime.h>
#include <cuda_bf16.h>
#include <cstdint>

// B=256, NU=NL=QU=QL=64. One CTA = 2 batch rows. 128 CTAs x 512 threads.
#define THREADS 512

// ---------------- smem byte offsets (all tiles SW128-swizzled) --------------
#define SM_P    0u          // [128 rows (ii,k)][64 bf16]   16 KB
#define SM_UH   16384u      // [256 rows (l*4+n)][64 bf16]  32 KB
#define SM_UL   49152u      //                              32 KB
#define SM_C1H  81920u      // [128 rows (ii*64+l)][64 bf16] 16 KB each
#define SM_C1L  98304u
#define SM_C2   114688u
#define SM_C3   131072u
#define SM_C4   147456u
#define SM_TH   163840u     // [64 j][64 bf16] 8 KB each
#define SM_T2   172032u
#define SM_T3   180224u
#define SM_T4   188416u
#define SM_LS   SM_UH       // overlay: [128 il][65 f32] (U dead by then)
#define SM_MISC 196608u
#define SMEM_TOTAL (SM_MISC + 2048u)   // 198656 B

__device__ __forceinline__ uint32_t sw128(uint32_t o) { return o ^ ((o >> 3) & 0x70u); }

__device__ __forceinline__ uint32_t smem_u32(const void* p) {
    uint32_t a;
    asm("{ .reg .u64 t; cvta.to.shared.u64 t, %1; cvt.u32.u64 %0, t; }" : "=r"(a) : "l"(p));
    return a;
}

// m16n8k16 row.col bf16 -> f32 (sm_80-baseline PTX; HMMA on Blackwell)
__device__ __forceinline__ void mma16816(float acc[4], const uint32_t a[4],
                                         uint32_t b0, uint32_t b1) {
    asm volatile(
        "mma.sync.aligned.m16n8k16.row.col.f32.bf16.bf16.f32 "
        "{%0,%1,%2,%3}, {%4,%5,%6,%7}, {%8,%9}, {%0,%1,%2,%3};"
        : "+f"(acc[0]), "+f"(acc[1]), "+f"(acc[2]), "+f"(acc[3])
        : "r"(a[0]), "r"(a[1]), "r"(a[2]), "r"(a[3]), "r"(b0), "r"(b1));
}

__device__ __forceinline__ void ldmx4(uint32_t r[4], uint32_t addr) {
    asm volatile("ldmatrix.sync.aligned.m8n8.x4.shared.b16 {%0,%1,%2,%3}, [%4];"
                 : "=r"(r[0]), "=r"(r[1]), "=r"(r[2]), "=r"(r[3]) : "r"(addr));
}

__global__ void __launch_bounds__(THREADS, 1)
drn_fused(const float* __restrict__ P, const float* __restrict__ weight,
          const float* __restrict__ bias_abs, const float* __restrict__ bias_q,
          const float* __restrict__ lam_abs, const float* __restrict__ lam_q,
          float* __restrict__ out)
{
    extern __shared__ __align__(16) char sm[];
    const uint32_t smb = smem_u32(sm);
    float* a0inv = (float*)(sm + SM_MISC);          // 128 floats
    float* sBa   = (float*)(sm + SM_MISC + 512);
    float* sBq   = (float*)(sm + SM_MISC + 768);
    float* sLa   = (float*)(sm + SM_MISC + 1024);
    float* sLq   = (float*)(sm + SM_MISC + 1280);

    const int tid = threadIdx.x;
    const int i0  = blockIdx.x * 2;

    // ---- fill P tile (bf16) + row sums (4 threads per row) -----------------
    {
        const int r = tid >> 2, qh = tid & 3;
        const float* src = P + ((size_t)(i0 + (r >> 6)) * 64 + (r & 63)) * 64 + qh * 16;
        float s = 0.f;
        #pragma unroll
        for (int q = 0; q < 4; ++q) {
            const float4 f = ((const float4*)src)[q];
            s += f.x + f.y + f.z + f.w;
            const uint32_t off = (uint32_t)r * 128 + (qh * 16 + q * 4) * 2;
            *(__nv_bfloat162*)(sm + SM_P + sw128(off))     = __floats2bfloat162_rn(f.x, f.y);
            *(__nv_bfloat162*)(sm + SM_P + sw128(off + 4)) = __floats2bfloat162_rn(f.z, f.w);
        }
        s += __shfl_xor_sync(0xffffffffu, s, 1);
        s += __shfl_xor_sync(0xffffffffu, s, 2);
        if (qh == 0) a0inv[r] = 1.0f / s;
    }

    // ---- fill U table hi/lo: row r = l*4+n holds u^(n+1), u=((l-m)/64)^2 ---
    {
        const int r = tid >> 1, h = tid & 1, l = r >> 2, n = r & 3;
        #pragma unroll 4
        for (int m2 = 0; m2 < 16; ++m2) {
            const int m = h * 32 + m2 * 2;
            float d0 = (float)(l - m) * (1.f / 64.f);
            float d1 = (float)(l - m - 1) * (1.f / 64.f);
            float u0 = d0 * d0, u1 = d1 * d1;
            float w0 = u0 * u0, w1 = u1 * u1;
            float v0 = (n == 0) ? u0 : (n == 1) ? w0 : (n == 2) ? w0 * u0 : w0 * w0;
            float v1 = (n == 0) ? u1 : (n == 1) ? w1 : (n == 2) ? w1 * u1 : w1 * w1;
            const __nv_bfloat162 hi = __floats2bfloat162_rn(v0, v1);
            const float r0 = v0 - __bfloat162float(hi.x);
            const float r1 = v1 - __bfloat162float(hi.y);
            const uint32_t off = (uint32_t)r * 128 + m * 2;
            *(__nv_bfloat162*)(sm + SM_UH + sw128(off)) = hi;
            *(__nv_bfloat162*)(sm + SM_UL + sw128(off)) = __floats2bfloat162_rn(r0, r1);
        }
    }

    // ---- fill T power tiles: row j holds t^n[j,k], t = -w ------------------
    {
        const int j = tid >> 3, kq = (tid & 7) * 8;
        const float* wr = weight + j * 64 + kq;
        #pragma unroll
        for (int q = 0; q < 4; ++q) {
            const float t0 = -wr[q * 2], t1 = -wr[q * 2 + 1];
            const float s0 = t0 * t0,   s1 = t1 * t1;
            const uint32_t off = (uint32_t)j * 128 + (kq + q * 2) * 2;
            *(__nv_bfloat162*)(sm + SM_TH + sw128(off)) = __floats2bfloat162_rn(t0, t1);
            *(__nv_bfloat162*)(sm + SM_T2 + sw128(off)) = __floats2bfloat162_rn(s0, s1);
            *(__nv_bfloat162*)(sm + SM_T3 + sw128(off)) = __floats2bfloat162_rn(s0 * t0, s1 * t1);
            *(__nv_bfloat162*)(sm + SM_T4 + sw128(off)) = __floats2bfloat162_rn(s0 * s0, s1 * s1);
        }
    }
    if (tid < 64) {
        sBa[tid] = bias_abs[tid]; sBq[tid] = bias_q[tid];
        sLa[tid] = lam_abs[tid];  sLq[tid] = lam_q[tid];
    }
    __syncthreads();

    const int lane = tid & 31, wid = tid >> 5;
    const int g = lane >> 2, c = lane & 3;
    const int mw = wid & 7, nh = wid >> 3;     // M-tile, N-half
    const int mr = mw * 16;

    // ldmatrix lane->address maps (relative byte offsets, pre-swizzle)
    // A (m16k16): m0 rows0-7/k0-7, m1 rows8-15/k0-7, m2 rows0-7/k8-15, m3 rows8-15/k8-15
    const uint32_t aBase = (uint32_t)(mr + (lane & 7) + ((lane >> 3) & 1) * 8) * 128
                           + (uint32_t)(lane >> 4) * 16;
    // B (two n8k16 blocks): m0 b0(t), m1 b1(t), m2 b0(t+1), m3 b1(t+1)
    const uint32_t bBase = (uint32_t)((lane & 7) + (lane >> 4) * 8) * 128
                           + (uint32_t)((lane >> 3) & 1) * 16;

    // Hoisted A fragments for GEMM1 (P tile, invariant over ch/pass)
    uint32_t afr[4][4];
    #pragma unroll
    for (int ks = 0; ks < 4; ++ks)
        ldmx4(afr[ks], smb + SM_P + sw128(aBase + ks * 32));

    // ================= GEMM1: moments -> cumulants -> C tiles ===============
    #pragma unroll 1
    for (int ch = 0; ch < 4; ++ch) {
        float acc[4][4];
        #pragma unroll
        for (int t = 0; t < 4; ++t)
            acc[t][0] = acc[t][1] = acc[t][2] = acc[t][3] = 0.f;

        #pragma unroll
        for (int pass = 0; pass < 2; ++pass) {
            const uint32_t SB = pass ? SM_UL : SM_UH;
            #pragma unroll
            for (int ks = 0; ks < 4; ++ks) {
                #pragma unroll
                for (int tp = 0; tp < 2; ++tp) {
                    const int t0 = nh * 4 + tp * 2;
                    uint32_t b[4];
                    ldmx4(b, smb + SB + sw128(bBase + (uint32_t)(ch * 64 + t0 * 8) * 128
                                              + ks * 32));
                    mma16816(acc[tp * 2 + 0], afr[ks], b[0], b[1]);
                    mma16816(acc[tp * 2 + 1], afr[ks], b[2], b[3]);
                }
            }
        }
        // epilogue: lane-pair exchange, fp32 cumulants, bf16 C stores
        #pragma unroll
        for (int tt = 0; tt < 4; ++tt) {
            const float r0 = __shfl_xor_sync(0xffffffffu, acc[tt][0], 1);
            const float r1 = __shfl_xor_sync(0xffffffffu, acc[tt][1], 1);
            const float r2 = __shfl_xor_sync(0xffffffffu, acc[tt][2], 1);
            const float r3 = __shfl_xor_sync(0xffffffffu, acc[tt][3], 1);
            int row; float M1, M2, M3, M4;
            if ((c & 1) == 0) { row = mr + g;     M1 = acc[tt][0]; M2 = acc[tt][1]; M3 = r0; M4 = r1; }
            else              { row = mr + g + 8; M1 = r2; M2 = r3; M3 = acc[tt][2]; M4 = acc[tt][3]; }
            const int l = ch * 16 + (nh * 4 + tt) * 2 + (c >> 1);
            const float ai = a0inv[row];
            const float m1 = M1 * ai, m2 = M2 * ai, m3 = M3 * ai, m4 = M4 * ai;
            const float m1s = m1 * m1;
            const float c1 = m1;
            const float c2 = 0.5f * (m2 - m1s);
            const float c3 = (1.f / 6.f) * (m3 - 3.f * m1 * m2 + 2.f * m1s * m1);
            const float c4 = (1.f / 24.f) * (m4 - 4.f * m1 * m3 - 3.f * m2 * m2
                                             + 12.f * m1s * m2 - 6.f * m1s * m1s);
            const uint32_t off =
                (uint32_t)(((row >> 6) * 64 + l) * 128 + (row & 63) * 2);
            const __nv_bfloat16 c1h = __float2bfloat16_rn(c1);
            *(__nv_bfloat16*)(sm + SM_C1H + sw128(off)) = c1h;
            *(__nv_bfloat16*)(sm + SM_C1L + sw128(off)) =
                __float2bfloat16_rn(c1 - __bfloat162float(c1h));
            *(__nv_bfloat16*)(sm + SM_C2 + sw128(off)) = __float2bfloat16_rn(c2);
            *(__nv_bfloat16*)(sm + SM_C3 + sw128(off)) = __float2bfloat16_rn(c3);
            *(__nv_bfloat16*)(sm + SM_C4 + sw128(off)) = __float2bfloat16_rn(c4);
        }
    }
    __syncthreads();

    // ================= GEMM2: logsum^T[(ii,l), j] ============================
    {
        float acc[4][4];
        #pragma unroll
        for (int t = 0; t < 4; ++t)
            acc[t][0] = acc[t][1] = acc[t][2] = acc[t][3] = 0.f;

        const uint32_t pA[5] = {SM_C1H, SM_C1L, SM_C2, SM_C3, SM_C4};
        const uint32_t pB[5] = {SM_TH,  SM_TH,  SM_T2, SM_T3, SM_T4};
        #pragma unroll 1
        for (int p = 0; p < 5; ++p) {
            #pragma unroll
            for (int ks = 0; ks < 4; ++ks) {
                uint32_t a[4];
                ldmx4(a, smb + pA[p] + sw128(aBase + ks * 32));
                #pragma unroll
                for (int tp = 0; tp < 2; ++tp) {
                    const int t0 = nh * 4 + tp * 2;
                    uint32_t b[4];
                    ldmx4(b, smb + pB[p] + sw128(bBase + (uint32_t)(t0 * 8) * 128
                                                 + ks * 32));
                    mma16816(acc[tp * 2 + 0], a, b[0], b[1]);
                    mma16816(acc[tp * 2 + 1], a, b[2], b[3]);
                }
            }
        }

        // epilogue: + exponent_B, stage to sLs
        float* ls = (float*)(sm + SM_LS);
        const int rowA = mr + g, rowB = rowA + 8;
        const float slA = (float)(rowA & 63) * (1.f / 64.f);
        const float slB = (float)(rowB & 63) * (1.f / 64.f);
        #pragma unroll
        for (int tt = 0; tt < 4; ++tt) {
            const int j0 = (nh * 4 + tt) * 8 + c * 2, j1 = j0 + 1;
            const float bq0 = sBq[j0], lq0 = sLq[j0], ba0 = sBa[j0], la0 = sLa[j0];
            const float bq1 = sBq[j1], lq1 = sLq[j1], ba1 = sBa[j1], la1 = sLa[j1];
            float d;
            d = slA - lq0; const float e00 = acc[tt][0] - bq0 * d * d - ba0 * fabsf(slA - la0);
            d = slA - lq1; const float e01 = acc[tt][1] - bq1 * d * d - ba1 * fabsf(slA - la1);
            d = slB - lq0; const float e10 = acc[tt][2] - bq0 * d * d - ba0 * fabsf(slB - la0);
            d = slB - lq1; const float e11 = acc[tt][3] - bq1 * d * d - ba1 * fabsf(slB - la1);
            ls[rowA * 65 + j0] = e00; ls[rowA * 65 + j1] = e01;
            ls[rowB * 65 + j0] = e10; ls[rowB * 65 + j1] = e11;
        }
    }
    __syncthreads();

    // ================= softmax over l, write out (4 threads per row) ========
    {
        const float* ls = (const float*)(sm + SM_LS);
        const int rid = tid >> 2, h = tid & 3;
        const int ii = rid >> 6, j = rid & 63;
        const int base = ii * 64 + h * 16;
        float v[16], mx = -1e30f;
        #pragma unroll
        for (int q = 0; q < 16; ++q) {
            v[q] = ls[(base + q) * 65 + j];
            mx = fmaxf(mx, v[q]);
        }
        mx = fmaxf(mx, __shfl_xor_sync(0xffffffffu, mx, 1));
        mx = fmaxf(mx, __shfl_xor_sync(0xffffffffu, mx, 2));
        float s = 0.f;
        #pragma unroll
        for (int q = 0; q < 16; ++q) { v[q] = __expf(v[q] - mx); s += v[q]; }
        s += __shfl_xor_sync(0xffffffffu, s, 1);
        s += __shfl_xor_sync(0xffffffffu, s, 2);
        const float inv = 1.0f / s;
        float4* ob = (float4*)(out + ((size_t)(i0 + ii) * 64 + j) * 64 + h * 16);
        #pragma unroll
        for (int q = 0; q < 4; ++q)
            ob[q] = make_float4(v[4 * q] * inv, v[4 * q + 1] * inv,
                                v[4 * q + 2] * inv, v[4 * q + 3] * inv);
    }
}

// ---------------------------------------------------------------------------
extern "C" void kernel_launch(void* const* d_in, const int* in_sizes, int n_in,
                              void* d_out, int out_size)
{
    const float* P        = (const float*)d_in[0];
    const float* weight   = (const float*)d_in[1];
    const float* bias_abs = (const float*)d_in[2];
    const float* bias_q   = (const float*)d_in[3];
    const float* lam_abs  = (const float*)d_in[4];
    const float* lam_q    = (const float*)d_in[5];
    float* out = (float*)d_out;

    cudaFuncSetAttribute(drn_fused, cudaFuncAttributeMaxDynamicSharedMemorySize,
                         SMEM_TOTAL);
    drn_fused<<<128, THREADS, SMEM_TOTAL>>>(P, weight, bias_abs, bias_q,
                                            lam_abs, lam_q, out);
}

// round 6
// speedup vs baseline: 3.5237x; 1.1385x over previous
#include <cuda_runtime.h>
#include <cuda_bf16.h>
#include <cstdint>

// B=256, NU=NL=QU=QL=64. One CTA = 2 batch rows. 128 CTAs x 512 threads.
#define THREADS 512

// ---------------- smem byte offsets (all tiles SW128-swizzled) --------------
#define SM_P    0u          // [128 rows (ii,k)][64 bf16]       16 KB
#define SM_U    16384u      // [256 rows (l*4+n)][64 bf16]      32 KB
#define SM_C1   49152u      // [128 rows (ii*64+l)][64 bf16]    16 KB each
#define SM_C2   65536u
#define SM_C3   81920u
#define SM_C4   98304u
#define SM_TH   114688u     // [64 j][64 bf16] 8 KB each
#define SM_T2   122880u
#define SM_T3   131072u
#define SM_T4   139264u
#define SM_LS   147456u     // [128 il][65 f32] = 33280 B
#define SM_MISC 180736u
#define SMEM_TOTAL (SM_MISC + 2048u)   // 182784 B

__device__ __forceinline__ uint32_t sw128(uint32_t o) { return o ^ ((o >> 3) & 0x70u); }

__device__ __forceinline__ uint32_t smem_u32(const void* p) {
    uint32_t a;
    asm("{ .reg .u64 t; cvta.to.shared.u64 t, %1; cvt.u32.u64 %0, t; }" : "=r"(a) : "l"(p));
    return a;
}

// m16n8k16 row.col bf16 -> f32 (sm_80-baseline PTX; HMMA on Blackwell)
__device__ __forceinline__ void mma16816(float acc[4], const uint32_t a[4],
                                         uint32_t b0, uint32_t b1) {
    asm volatile(
        "mma.sync.aligned.m16n8k16.row.col.f32.bf16.bf16.f32 "
        "{%0,%1,%2,%3}, {%4,%5,%6,%7}, {%8,%9}, {%0,%1,%2,%3};"
        : "+f"(acc[0]), "+f"(acc[1]), "+f"(acc[2]), "+f"(acc[3])
        : "r"(a[0]), "r"(a[1]), "r"(a[2]), "r"(a[3]), "r"(b0), "r"(b1));
}

__device__ __forceinline__ void ldmx4(uint32_t r[4], uint32_t addr) {
    asm volatile("ldmatrix.sync.aligned.m8n8.x4.shared.b16 {%0,%1,%2,%3}, [%4];"
                 : "=r"(r[0]), "=r"(r[1]), "=r"(r[2]), "=r"(r[3]) : "r"(addr));
}

__global__ void __launch_bounds__(THREADS, 1)
drn_fused(const float* __restrict__ P, const float* __restrict__ weight,
          const float* __restrict__ bias_abs, const float* __restrict__ bias_q,
          const float* __restrict__ lam_abs, const float* __restrict__ lam_q,
          float* __restrict__ out)
{
    extern __shared__ __align__(16) char sm[];
    const uint32_t smb = smem_u32(sm);
    float* a0inv = (float*)(sm + SM_MISC);          // 128 floats
    float* sBa   = (float*)(sm + SM_MISC + 512);
    float* sBq   = (float*)(sm + SM_MISC + 768);
    float* sLa   = (float*)(sm + SM_MISC + 1024);
    float* sLq   = (float*)(sm + SM_MISC + 1280);

    const int tid = threadIdx.x;
    const int i0  = blockIdx.x * 2;

    // ---- fill P tile (bf16) + row sums (4 threads per row) -----------------
    {
        const int r = tid >> 2, qh = tid & 3;
        const float* src = P + ((size_t)(i0 + (r >> 6)) * 64 + (r & 63)) * 64 + qh * 16;
        float s = 0.f;
        #pragma unroll
        for (int q = 0; q < 4; ++q) {
            const float4 f = ((const float4*)src)[q];
            s += f.x + f.y + f.z + f.w;
            const uint32_t off = (uint32_t)r * 128 + (qh * 16 + q * 4) * 2;
            *(__nv_bfloat162*)(sm + SM_P + sw128(off))     = __floats2bfloat162_rn(f.x, f.y);
            *(__nv_bfloat162*)(sm + SM_P + sw128(off + 4)) = __floats2bfloat162_rn(f.z, f.w);
        }
        s += __shfl_xor_sync(0xffffffffu, s, 1);
        s += __shfl_xor_sync(0xffffffffu, s, 2);
        if (qh == 0) a0inv[r] = 1.0f / s;
    }

    // ---- fill U table: row r = l*4+n holds u^(n+1), u=((l-m)/64)^2 ---------
    {
        const int r = tid >> 1, h = tid & 1, l = r >> 2, n = r & 3;
        #pragma unroll 4
        for (int m2 = 0; m2 < 16; ++m2) {
            const int m = h * 32 + m2 * 2;
            float d0 = (float)(l - m) * (1.f / 64.f);
            float d1 = (float)(l - m - 1) * (1.f / 64.f);
            float u0 = d0 * d0, u1 = d1 * d1;
            float w0 = u0 * u0, w1 = u1 * u1;
            float v0 = (n == 0) ? u0 : (n == 1) ? w0 : (n == 2) ? w0 * u0 : w0 * w0;
            float v1 = (n == 0) ? u1 : (n == 1) ? w1 : (n == 2) ? w1 * u1 : w1 * w1;
            const uint32_t off = (uint32_t)r * 128 + m * 2;
            *(__nv_bfloat162*)(sm + SM_U + sw128(off)) = __floats2bfloat162_rn(v0, v1);
        }
    }

    // ---- fill T power tiles: row j holds t^n[j,k], t = -w ------------------
    {
        const int j = tid >> 3, kq = (tid & 7) * 8;
        const float* wr = weight + j * 64 + kq;
        #pragma unroll
        for (int q = 0; q < 4; ++q) {
            const float t0 = -wr[q * 2], t1 = -wr[q * 2 + 1];
            const float s0 = t0 * t0,   s1 = t1 * t1;
            const uint32_t off = (uint32_t)j * 128 + (kq + q * 2) * 2;
            *(__nv_bfloat162*)(sm + SM_TH + sw128(off)) = __floats2bfloat162_rn(t0, t1);
            *(__nv_bfloat162*)(sm + SM_T2 + sw128(off)) = __floats2bfloat162_rn(s0, s1);
            *(__nv_bfloat162*)(sm + SM_T3 + sw128(off)) = __floats2bfloat162_rn(s0 * t0, s1 * t1);
            *(__nv_bfloat162*)(sm + SM_T4 + sw128(off)) = __floats2bfloat162_rn(s0 * s0, s1 * s1);
        }
    }
    if (tid < 64) {
        sBa[tid] = bias_abs[tid]; sBq[tid] = bias_q[tid];
        sLa[tid] = lam_abs[tid];  sLq[tid] = lam_q[tid];
    }
    __syncthreads();

    const int lane = tid & 31, wid = tid >> 5;
    const int g = lane >> 2, c = lane & 3;
    const int mw = wid & 3, nq = wid >> 2;   // M-tile group (M=32), N-quarter
    const int mr = mw * 32;

    // ldmatrix lane->address maps (relative byte offsets, pre-swizzle)
    const uint32_t aRow = (uint32_t)((lane & 7) + ((lane >> 3) & 1) * 8) * 128
                          + (uint32_t)(lane >> 4) * 16;
    const uint32_t bRow = (uint32_t)((lane & 7) + (lane >> 4) * 8) * 128
                          + (uint32_t)((lane >> 3) & 1) * 16;

    // Hoisted A fragments (P tile rows mr..mr+32), invariant over GEMM1
    uint32_t afr[2][4][4];
    #pragma unroll
    for (int mt = 0; mt < 2; ++mt)
        #pragma unroll
        for (int ks = 0; ks < 4; ++ks)
            ldmx4(afr[mt][ks],
                  smb + SM_P + sw128((uint32_t)(mr + mt * 16) * 128 + aRow + ks * 32));

    // ================= GEMM1: moments -> cumulants -> C tiles ===============
    #pragma unroll 1
    for (int nbp = 0; nbp < 4; ++nbp) {
        float acc[2][2][4];
        #pragma unroll
        for (int mt = 0; mt < 2; ++mt)
            #pragma unroll
            for (int bk = 0; bk < 2; ++bk)
                acc[mt][bk][0] = acc[mt][bk][1] = acc[mt][bk][2] = acc[mt][bk][3] = 0.f;

        #pragma unroll
        for (int ks = 0; ks < 4; ++ks) {
            uint32_t b[4];
            ldmx4(b, smb + SM_U + sw128((uint32_t)(nq * 64 + nbp * 16) * 128
                                        + bRow + ks * 32));
            #pragma unroll
            for (int mt = 0; mt < 2; ++mt) {
                mma16816(acc[mt][0], afr[mt][ks], b[0], b[1]);
                mma16816(acc[mt][1], afr[mt][ks], b[2], b[3]);
            }
        }
        // epilogue: lane-pair exchange, fp32 cumulants, bf16 C stores
        #pragma unroll
        for (int mt = 0; mt < 2; ++mt) {
            #pragma unroll
            for (int bk = 0; bk < 2; ++bk) {
                float* a = acc[mt][bk];
                const float r0 = __shfl_xor_sync(0xffffffffu, a[0], 1);
                const float r1 = __shfl_xor_sync(0xffffffffu, a[1], 1);
                const float r2 = __shfl_xor_sync(0xffffffffu, a[2], 1);
                const float r3 = __shfl_xor_sync(0xffffffffu, a[3], 1);
                int row; float M1, M2, M3, M4;
                if ((c & 1) == 0) { row = mr + mt * 16 + g;     M1 = a[0]; M2 = a[1]; M3 = r0; M4 = r1; }
                else              { row = mr + mt * 16 + g + 8; M1 = r2; M2 = r3; M3 = a[2]; M4 = a[3]; }
                const int l = nq * 16 + nbp * 4 + bk * 2 + (c >> 1);
                const float ai = a0inv[row];
                const float m1 = M1 * ai, m2 = M2 * ai, m3 = M3 * ai, m4 = M4 * ai;
                const float m1s = m1 * m1;
                const float c2 = 0.5f * (m2 - m1s);
                const float c3 = (1.f / 6.f) * (m3 - 3.f * m1 * m2 + 2.f * m1s * m1);
                const float c4 = (1.f / 24.f) * (m4 - 4.f * m1 * m3 - 3.f * m2 * m2
                                                 + 12.f * m1s * m2 - 6.f * m1s * m1s);
                const uint32_t off =
                    (uint32_t)(((row >> 6) * 64 + l) * 128 + (row & 63) * 2);
                *(__nv_bfloat16*)(sm + SM_C1 + sw128(off)) = __float2bfloat16_rn(m1);
                *(__nv_bfloat16*)(sm + SM_C2 + sw128(off)) = __float2bfloat16_rn(c2);
                *(__nv_bfloat16*)(sm + SM_C3 + sw128(off)) = __float2bfloat16_rn(c3);
                *(__nv_bfloat16*)(sm + SM_C4 + sw128(off)) = __float2bfloat16_rn(c4);
            }
        }
    }
    __syncthreads();

    // ================= GEMM2: logsum^T[(ii,l), j] ============================
    {
        float acc[2][2][4];
        #pragma unroll
        for (int mt = 0; mt < 2; ++mt)
            #pragma unroll
            for (int bk = 0; bk < 2; ++bk)
                acc[mt][bk][0] = acc[mt][bk][1] = acc[mt][bk][2] = acc[mt][bk][3] = 0.f;

        const uint32_t pA[4] = {SM_C1, SM_C2, SM_C3, SM_C4};
        const uint32_t pB[4] = {SM_TH, SM_T2, SM_T3, SM_T4};
        #pragma unroll 1
        for (int p = 0; p < 4; ++p) {
            #pragma unroll
            for (int ks = 0; ks < 4; ++ks) {
                uint32_t b[4];
                ldmx4(b, smb + pB[p] + sw128((uint32_t)(nq * 16) * 128 + bRow + ks * 32));
                #pragma unroll
                for (int mt = 0; mt < 2; ++mt) {
                    uint32_t a[4];
                    ldmx4(a, smb + pA[p] + sw128((uint32_t)(mr + mt * 16) * 128
                                                 + aRow + ks * 32));
                    mma16816(acc[mt][0], a, b[0], b[1]);
                    mma16816(acc[mt][1], a, b[2], b[3]);
                }
            }
        }

        // epilogue: + exponent_B, stage to sLs
        float* ls = (float*)(sm + SM_LS);
        #pragma unroll
        for (int mt = 0; mt < 2; ++mt) {
            const int rowA = mr + mt * 16 + g, rowB = rowA + 8;
            const float slA = (float)(rowA & 63) * (1.f / 64.f);
            const float slB = (float)(rowB & 63) * (1.f / 64.f);
            #pragma unroll
            for (int bk = 0; bk < 2; ++bk) {
                const float* a = acc[mt][bk];
                const int j0 = nq * 16 + bk * 8 + c * 2, j1 = j0 + 1;
                const float bq0 = sBq[j0], lq0 = sLq[j0], ba0 = sBa[j0], la0 = sLa[j0];
                const float bq1 = sBq[j1], lq1 = sLq[j1], ba1 = sBa[j1], la1 = sLa[j1];
                float d;
                d = slA - lq0; ls[rowA * 65 + j0] = a[0] - bq0 * d * d - ba0 * fabsf(slA - la0);
                d = slA - lq1; ls[rowA * 65 + j1] = a[1] - bq1 * d * d - ba1 * fabsf(slA - la1);
                d = slB - lq0; ls[rowB * 65 + j0] = a[2] - bq0 * d * d - ba0 * fabsf(slB - la0);
                d = slB - lq1; ls[rowB * 65 + j1] = a[3] - bq1 * d * d - ba1 * fabsf(slB - la1);
            }
        }
    }
    __syncthreads();

    // ================= softmax over l, write out (4 threads per row) ========
    {
        const float* ls = (const float*)(sm + SM_LS);
        const int rid = tid >> 2, h = tid & 3;
        const int ii = rid >> 6, j = rid & 63;
        const int base = ii * 64 + h * 16;
        float v[16], mx = -1e30f;
        #pragma unroll
        for (int q = 0; q < 16; ++q) {
            v[q] = ls[(base + q) * 65 + j];
            mx = fmaxf(mx, v[q]);
        }
        mx = fmaxf(mx, __shfl_xor_sync(0xffffffffu, mx, 1));
        mx = fmaxf(mx, __shfl_xor_sync(0xffffffffu, mx, 2));
        float s = 0.f;
        #pragma unroll
        for (int q = 0; q < 16; ++q) { v[q] = __expf(v[q] - mx); s += v[q]; }
        s += __shfl_xor_sync(0xffffffffu, s, 1);
        s += __shfl_xor_sync(0xffffffffu, s, 2);
        const float inv = 1.0f / s;
        float4* ob = (float4*)(out + ((size_t)(i0 + ii) * 64 + j) * 64 + h * 16);
        #pragma unroll
        for (int q = 0; q < 4; ++q)
            ob[q] = make_float4(v[4 * q] * inv, v[4 * q + 1] * inv,
                                v[4 * q + 2] * inv, v[4 * q + 3] * inv);
    }
}

// ---------------------------------------------------------------------------
extern "C" void kernel_launch(void* const* d_in, const int* in_sizes, int n_in,
                              void* d_out, int out_size)
{
    const float* P        = (const float*)d_in[0];
    const float* weight   = (const float*)d_in[1];
    const float* bias_abs = (const float*)d_in[2];
    const float* bias_q   = (const float*)d_in[3];
    const float* lam_abs  = (const float*)d_in[4];
    const float* lam_q    = (const float*)d_in[5];
    float* out = (float*)d_out;

    cudaFuncSetAttribute(drn_fused, cudaFuncAttributeMaxDynamicSharedMemorySize,
                         SMEM_TOTAL);
    drn_fused<<<128, THREADS, SMEM_TOTAL>>>(P, weight, bias_abs, bias_q,
                                            lam_abs, lam_q, out);
}